// round 5
// baseline (speedup 1.0000x reference)
#include <cuda_runtime.h>
#include <math.h>

#define PI_HALF 1.57079632679489662f
#define NT 64

// ---------------- scratch (pixel-major [N][B]) ----------------
__device__ float g_y0[729 * 128];
__device__ float g_y1[81 * 128];
__device__ float g_y2[9 * 128];

// Per-sample min/max atomic keys, 128B-padded. Identity 0 for atomicMax.
__device__ unsigned g_kx0[128 * 32];
__device__ unsigned g_kn0[128 * 32];
__device__ unsigned g_kx1[128 * 32];
__device__ unsigned g_kn1[128 * 32];

// ---------------- software grid barrier (self-resetting) ----------------
__device__ unsigned g_count = 0;
__device__ unsigned g_gen = 0;

__device__ __forceinline__ void grid_barrier()
{
    __threadfence();
    __syncthreads();
    if (threadIdx.x == 0) {
        volatile unsigned* gen = &g_gen;
        const unsigned target = *gen + 1;
        const unsigned arrived = atomicAdd(&g_count, 1) + 1;
        if (arrived == gridDim.x) {
            g_count = 0;
            __threadfence();
            atomicAdd(&g_gen, 1);
        } else {
            while ((int)(*gen - target) < 0) __nanosleep(32);
        }
        __threadfence();
    }
    __syncthreads();
}

// ---------------- monotonic float<->uint key ----------------
__device__ __forceinline__ unsigned fkey(float f)
{
    unsigned u = __float_as_uint(f);
    return u ^ ((unsigned)((int)u >> 31) | 0x80000000u);
}
__device__ __forceinline__ float funkey(unsigned k)
{
    unsigned u = (k & 0x80000000u) ? (k ^ 0x80000000u) : ~k;
    return __uint_as_float(u);
}

// ---------------- packed f32x2 FMA ----------------
__device__ __forceinline__ float2 ffma2(float2 a, float2 b, float2 c)
{
    unsigned long long au = *reinterpret_cast<unsigned long long*>(&a);
    unsigned long long bu = *reinterpret_cast<unsigned long long*>(&b);
    unsigned long long cu = *reinterpret_cast<unsigned long long*>(&c);
    unsigned long long du;
    asm("fma.rn.f32x2 %0, %1, %2, %3;" : "=l"(du) : "l"(au), "l"(bu), "l"(cu));
    return *reinterpret_cast<float2*>(&du);
}

// Stage Wm[n] ([s][a][p][c]) permuted so each a-row is 5 aligned float4s:
// (p,c) -> a*20 + (c>>1)*4 + (c&1)*2 + p.
__device__ __forceinline__ void stage_wm(const float* __restrict__ gWm,
                                         float* __restrict__ sWm, int tid)
{
    #pragma unroll
    for (int t = tid; t < 1400; t += NT) {
        const int s  = t / 200;
        const int r  = t - s * 200;
        const int a  = r / 20;
        const int r2 = r - a * 20;
        const int p  = r2 / 10;
        const int c  = r2 - p * 10;
        sWm[s * 200 + a * 20 + ((c >> 1) << 2) + ((c & 1) << 1) + p] = gWm[t];
    }
}

// Single-sample core (tail phases). e0/e1 precomputed.
__device__ __forceinline__ float mps_core(const float* e0, const float* e1,
                                          const float* __restrict__ w0c,
                                          const float* __restrict__ w0s,
                                          const float* __restrict__ sWm,
                                          const float* __restrict__ sWn)
{
    float v[10];
    #pragma unroll
    for (int a = 0; a < 10; a++)
        v[a] = fmaf(e1[0], w0s[a], e0[0] * w0c[a]);

    #pragma unroll
    for (int s = 0; s < 7; s++) {
        const float4* M = reinterpret_cast<const float4*>(sWm + s * 200);
        float2 acc[10];
        #pragma unroll
        for (int c = 0; c < 10; c++) acc[c] = make_float2(0.f, 0.f);
        #pragma unroll
        for (int a = 0; a < 10; a++) {
            const float2 va2 = make_float2(v[a], v[a]);
            const float4* Ma = M + a * 5;
            #pragma unroll
            for (int j = 0; j < 5; j++) {
                const float4 m = Ma[j];
                acc[2 * j]     = ffma2(va2, make_float2(m.x, m.y), acc[2 * j]);
                acc[2 * j + 1] = ffma2(va2, make_float2(m.z, m.w), acc[2 * j + 1]);
            }
        }
        const float ce = e0[s + 1], se = e1[s + 1];
        #pragma unroll
        for (int c = 0; c < 10; c++)
            v[c] = fmaf(se, acc[c].y, ce * acc[c].x);
    }

    float r = 0.f;
    #pragma unroll
    for (int a = 0; a < 10; a++)
        r = fmaf(v[a], fmaf(e1[8], sWn[2 * a + 1], e0[8] * sWn[2 * a]), r);
    return r;
}

// Two-sample core (phase 0). f0/f1: raw features; sincos computed lazily.
__device__ __forceinline__ void mps_core2(const float* f0, const float* f1,
                                          const float* __restrict__ w0c,
                                          const float* __restrict__ w0s,
                                          const float* __restrict__ sWm,
                                          const float* __restrict__ sWn,
                                          float& r0, float& r1)
{
    float c0, s0, c1, s1;
    __sincosf(f0[0] * PI_HALF, &s0, &c0);
    __sincosf(f1[0] * PI_HALF, &s1, &c1);

    float v0[10], v1[10];
    #pragma unroll
    for (int a = 0; a < 10; a++) {
        v0[a] = fmaf(s0, w0s[a], c0 * w0c[a]);
        v1[a] = fmaf(s1, w0s[a], c1 * w0c[a]);
    }

    #pragma unroll
    for (int s = 0; s < 7; s++) {
        float cn0, sn0, cn1, sn1;                  // consumed ~100 FFMA2s later
        __sincosf(f0[s + 1] * PI_HALF, &sn0, &cn0);
        __sincosf(f1[s + 1] * PI_HALF, &sn1, &cn1);

        const float4* M = reinterpret_cast<const float4*>(sWm + s * 200);
        float2 A0[10], A1[10];
        #pragma unroll
        for (int c = 0; c < 10; c++) { A0[c] = make_float2(0.f, 0.f); A1[c] = make_float2(0.f, 0.f); }
        #pragma unroll
        for (int a = 0; a < 10; a++) {
            const float2 va0 = make_float2(v0[a], v0[a]);
            const float2 va1 = make_float2(v1[a], v1[a]);
            const float4* Ma = M + a * 5;
            #pragma unroll
            for (int j = 0; j < 5; j++) {
                const float4 m = Ma[j];                 // one LDS.128, 4 FFMA2s
                const float2 mlo = make_float2(m.x, m.y);
                const float2 mhi = make_float2(m.z, m.w);
                A0[2 * j]     = ffma2(va0, mlo, A0[2 * j]);
                A0[2 * j + 1] = ffma2(va0, mhi, A0[2 * j + 1]);
                A1[2 * j]     = ffma2(va1, mlo, A1[2 * j]);
                A1[2 * j + 1] = ffma2(va1, mhi, A1[2 * j + 1]);
            }
        }
        #pragma unroll
        for (int c = 0; c < 10; c++) {
            v0[c] = fmaf(sn0, A0[c].y, cn0 * A0[c].x);
            v1[c] = fmaf(sn1, A1[c].y, cn1 * A1[c].x);
        }
    }

    float ce0, se0, ce1, se1;
    __sincosf(f0[8] * PI_HALF, &se0, &ce0);
    __sincosf(f1[8] * PI_HALF, &se1, &ce1);
    float acc0 = 0.f, acc1 = 0.f;
    #pragma unroll
    for (int a = 0; a < 10; a++) {
        acc0 = fmaf(v0[a], fmaf(se0, sWn[2 * a + 1], ce0 * sWn[2 * a]), acc0);
        acc1 = fmaf(v1[a], fmaf(se1, sWn[2 * a + 1], ce1 * sWn[2 * a]), acc1);
    }
    r0 = acc0; r1 = acc1;
}

// ---------------- single fused kernel ----------------
// launch_bounds(64, 6): 170-reg cap (no spills for the 2-sample core),
// 6 resident blocks/SM guaranteed -> grid = 6*SMs is barrier-safe.
__global__ void __launch_bounds__(NT, 6)
fused_lotenet(const float* __restrict__ x,
              const float* __restrict__ W00, const float* __restrict__ Wm0, const float* __restrict__ Wn0,
              const float* __restrict__ W01, const float* __restrict__ Wm1, const float* __restrict__ Wn1,
              const float* __restrict__ W02, const float* __restrict__ Wm2, const float* __restrict__ Wn2,
              const float* __restrict__ W03, const float* __restrict__ Wm3, const float* __restrict__ Wn3,
              float* __restrict__ out)
{
    __shared__ __align__(16) float sWm[1400];
    __shared__ float sW0[200];
    __shared__ float sWn[20];

    const int tid = threadIdx.x;
    const int bid = blockIdx.x;
    const int nblk = gridDim.x;

    // ---- Phase 0: layer-0 MPS. Block = pixel, thread = samples (tid, tid+64) ----
    for (int n = bid; n < 729; n += nblk) {
        __syncthreads();
        stage_wm(Wm0 + n * 1400, sWm, tid);
        if (tid < 20)      sW0[tid]      = W00[n * 20 + tid];
        else if (tid < 40) sWn[tid - 20] = Wn0[n * 20 + (tid - 20)];
        __syncthreads();

        const int i = n / 27, j = n - i * 27;
        float f0[9], f1[9];
        #pragma unroll
        for (int k = 0; k < 9; k++) {
            const int r = 3 * i + k / 3;
            const int c = 3 * j + (k - (k / 3) * 3);
            f0[k] = x[((size_t)tid * 81 + r) * 81 + c];
            f1[k] = x[((size_t)(tid + 64) * 81 + r) * 81 + c];
        }
        float y0v, y1v;
        mps_core2(f0, f1, sW0, sW0 + 10, sWm, sWn, y0v, y1v);
        g_y0[n * 128 + tid]      = y0v;
        g_y0[n * 128 + tid + 64] = y1v;
        atomicMax(&g_kx0[tid * 32], fkey(y0v));
        atomicMax(&g_kn0[tid * 32], ~fkey(y0v));
        atomicMax(&g_kx0[(tid + 64) * 32], fkey(y1v));
        atomicMax(&g_kn0[(tid + 64) * 32], ~fkey(y1v));
    }
    grid_barrier();

    // ---- Phase 1: layer-1 MPS. 162 blocks: pixel = bid>>1, sample half = bid&1 ----
    if (bid < 162) {
        const int n = bid >> 1;
        const int b = ((bid & 1) << 6) + tid;
        stage_wm(Wm1 + n * 1400, sWm, tid);
        if (tid < 20)      sW0[tid]      = W01[n * 20 + tid];
        else if (tid < 40) sWn[tid - 20] = Wn1[n * 20 + (tid - 20)];

        const float mn = funkey(~g_kn0[b * 32]);
        const float iv = 1.0f / (funkey(g_kx0[b * 32]) - mn);
        __syncthreads();

        float e0[9], e1[9];
        const int i = n / 9, j = n - i * 9;
        #pragma unroll
        for (int k = 0; k < 9; k++) {
            const int r = 3 * i + k / 3;
            const int c = 3 * j + (k - (k / 3) * 3);
            const float f = (g_y0[(r * 27 + c) * 128 + b] - mn) * iv;
            __sincosf(f * PI_HALF, &e1[k], &e0[k]);
        }
        const float y = mps_core(e0, e1, sW0, sW0 + 10, sWm, sWn);
        g_y1[n * 128 + b] = y;
        atomicMax(&g_kx1[b * 32], fkey(y));
        atomicMax(&g_kn1[b * 32], ~fkey(y));
    }
    grid_barrier();

    // ---- Phase 2: layer-2 MPS. 18 blocks. Block 100 resets L0 keys. ----
    if (bid < 18) {
        const int n = bid >> 1;
        const int b = ((bid & 1) << 6) + tid;
        stage_wm(Wm2 + n * 1400, sWm, tid);
        if (tid < 20)      sW0[tid]      = W02[n * 20 + tid];
        else if (tid < 40) sWn[tid - 20] = Wn2[n * 20 + (tid - 20)];

        const float mn = funkey(~g_kn1[b * 32]);
        const float iv = 1.0f / (funkey(g_kx1[b * 32]) - mn);
        __syncthreads();

        float e0[9], e1[9];
        const int i = n / 3, j = n - i * 3;
        #pragma unroll
        for (int k = 0; k < 9; k++) {
            const int r = 3 * i + k / 3;
            const int c = 3 * j + (k - (k / 3) * 3);
            const float f = (g_y1[(r * 9 + c) * 128 + b] - mn) * iv;
            __sincosf(f * PI_HALF, &e1[k], &e0[k]);
        }
        g_y2[n * 128 + b] = mps_core(e0, e1, sW0, sW0 + 10, sWm, sWn);
    } else if (bid == 100) {
        g_kx0[tid * 32] = 0;        g_kn0[tid * 32] = 0;
        g_kx0[(tid + 64) * 32] = 0; g_kn0[(tid + 64) * 32] = 0;
    }
    grid_barrier();

    // ---- Phase 3: final MPS. 20 blocks: o = bid>>1, half = bid&1.
    //      Block 100 resets L1 keys. ----
    if (bid < 20) {
        const int o = bid >> 1;
        const int b = ((bid & 1) << 6) + tid;
        stage_wm(Wm3, sWm, tid);
        #pragma unroll
        for (int t = tid; t < 200; t += NT) sW0[t] = W03[t];
        if (tid < 20) sWn[tid] = Wn3[tid];

        float yk[9];
        float mn = INFINITY, mx = -INFINITY;
        #pragma unroll
        for (int k = 0; k < 9; k++) {
            yk[k] = g_y2[k * 128 + b];
            mn = fminf(mn, yk[k]);
            mx = fmaxf(mx, yk[k]);
        }
        const float iv = 1.0f / (mx - mn);
        __syncthreads();

        float e0[9], e1[9];
        #pragma unroll
        for (int k = 0; k < 9; k++)
            __sincosf((yk[k] - mn) * iv * PI_HALF, &e1[k], &e0[k]);

        out[b * 10 + o] = mps_core(e0, e1, sW0 + o * 10, sW0 + 100 + o * 10, sWm, sWn);
    } else if (bid == 100) {
        g_kx1[tid * 32] = 0;        g_kn1[tid * 32] = 0;
        g_kx1[(tid + 64) * 32] = 0; g_kn1[(tid + 64) * 32] = 0;
    }
}

extern "C" void kernel_launch(void* const* d_in, const int* in_sizes, int n_in,
                              void* d_out, int out_size)
{
    const float* x   = (const float*)d_in[0];
    const float* W00 = (const float*)d_in[1];
    const float* Wm0 = (const float*)d_in[2];
    const float* Wn0 = (const float*)d_in[3];
    const float* W01 = (const float*)d_in[6];
    const float* Wm1 = (const float*)d_in[7];
    const float* Wn1 = (const float*)d_in[8];
    const float* W02 = (const float*)d_in[11];
    const float* Wm2 = (const float*)d_in[12];
    const float* Wn2 = (const float*)d_in[13];
    const float* W03 = (const float*)d_in[16];
    const float* Wm3 = (const float*)d_in[17];
    const float* Wn3 = (const float*)d_in[18];

    int nsm = 148;
    cudaDeviceGetAttribute(&nsm, cudaDevAttrMultiProcessorCount, 0);
    const int grid = 6 * nsm;   // __launch_bounds__(64,6): all resident

    fused_lotenet<<<grid, NT>>>(x, W00, Wm0, Wn0, W01, Wm1, Wn1,
                                W02, Wm2, Wn2, W03, Wm3, Wn3,
                                (float*)d_out);
}

// round 6
// speedup vs baseline: 1.3548x; 1.3548x over previous
#include <cuda_runtime.h>
#include <math.h>

#define PI_HALF 1.57079632679489662f
#define NT 128

// ---------------- scratch (pixel-major [N][B]) ----------------
__device__ float g_y0[729 * 128];
__device__ float g_y1[81 * 128];
__device__ float g_y2[9 * 128];

// Per-sample min/max atomic keys, 128B-padded. Identity 0 for atomicMax.
__device__ unsigned g_kx0[128 * 32];
__device__ unsigned g_kn0[128 * 32];
__device__ unsigned g_kx1[128 * 32];
__device__ unsigned g_kn1[128 * 32];

// ---------------- software grid barrier (self-resetting) ----------------
__device__ unsigned g_count = 0;
__device__ unsigned g_gen = 0;

__device__ __forceinline__ void grid_barrier()
{
    __threadfence();
    __syncthreads();
    if (threadIdx.x == 0) {
        volatile unsigned* gen = &g_gen;
        const unsigned target = *gen + 1;
        const unsigned arrived = atomicAdd(&g_count, 1) + 1;
        if (arrived == gridDim.x) {
            g_count = 0;
            __threadfence();
            atomicAdd(&g_gen, 1);
        } else {
            while ((int)(*gen - target) < 0) __nanosleep(32);
        }
        __threadfence();
    }
    __syncthreads();
}

// ---------------- monotonic float<->uint key ----------------
__device__ __forceinline__ unsigned fkey(float f)
{
    unsigned u = __float_as_uint(f);
    return u ^ ((unsigned)((int)u >> 31) | 0x80000000u);
}
__device__ __forceinline__ float funkey(unsigned k)
{
    unsigned u = (k & 0x80000000u) ? (k ^ 0x80000000u) : ~k;
    return __uint_as_float(u);
}

// ---------------- packed f32x2 FMA ----------------
__device__ __forceinline__ float2 ffma2(float2 a, float2 b, float2 c)
{
    unsigned long long au = *reinterpret_cast<unsigned long long*>(&a);
    unsigned long long bu = *reinterpret_cast<unsigned long long*>(&b);
    unsigned long long cu = *reinterpret_cast<unsigned long long*>(&c);
    unsigned long long du;
    asm("fma.rn.f32x2 %0, %1, %2, %3;" : "=l"(du) : "l"(au), "l"(bu), "l"(cu));
    return *reinterpret_cast<float2*>(&du);
}

// ---------------- cp.async helpers ----------------
__device__ __forceinline__ void cp_async16(float* sdst, const float* gsrc)
{
    unsigned saddr = (unsigned)__cvta_generic_to_shared(sdst);
    asm volatile("cp.async.cg.shared.global [%0], [%1], 16;" :: "r"(saddr), "l"(gsrc));
}
#define CP_COMMIT() asm volatile("cp.async.commit_group;" ::: "memory")
#define CP_WAIT0()  asm volatile("cp.async.wait_group 0;" ::: "memory")

// Permute index for Wm element t (layout [s][a][p][c]) into the compute
// layout: each a-row = 5 aligned float4s of (p0,p1) pairs over c.
__device__ __forceinline__ int wm_perm(int t)
{
    const int s  = t / 200;
    const int r  = t - s * 200;
    const int a  = r / 20;
    const int r2 = r - a * 20;
    const int p  = r2 / 10;
    const int c  = r2 - p * 10;
    return s * 200 + a * 20 + ((c >> 1) << 2) + ((c & 1) << 1) + p;
}

// Stage Wm directly from global (phase 0).
__device__ __forceinline__ void stage_wm_g(const float* __restrict__ gWm,
                                           float* __restrict__ sWm, int tid)
{
    #pragma unroll
    for (int t = tid; t < 1400; t += NT) sWm[wm_perm(t)] = gWm[t];
}

// Permute Wm from raw smem (arrived via cp.async) into compute layout.
__device__ __forceinline__ void stage_wm_s(const float* __restrict__ sRaw,
                                           float* __restrict__ sWm, int tid)
{
    #pragma unroll
    for (int t = tid; t < 1400; t += NT) sWm[wm_perm(t)] = sRaw[t];
}

// Single-sample MPS core, lazy sincos. f[9]: raw feature values.
__device__ __forceinline__ float mps_core(const float* f,
                                          const float* __restrict__ w0c,
                                          const float* __restrict__ w0s,
                                          const float* __restrict__ sWm,
                                          const float* __restrict__ sWn)
{
    float c0, s0;
    __sincosf(f[0] * PI_HALF, &s0, &c0);
    float v[10];
    #pragma unroll
    for (int a = 0; a < 10; a++)
        v[a] = fmaf(s0, w0s[a], c0 * w0c[a]);

    #pragma unroll
    for (int s = 0; s < 7; s++) {
        float cn, sn;                       // MUFU overlapped with 100 FFMA2s
        __sincosf(f[s + 1] * PI_HALF, &sn, &cn);

        const float4* M = reinterpret_cast<const float4*>(sWm + s * 200);
        float2 acc[10];
        #pragma unroll
        for (int c = 0; c < 10; c++) acc[c] = make_float2(0.f, 0.f);
        #pragma unroll
        for (int a = 0; a < 10; a++) {
            const float2 va2 = make_float2(v[a], v[a]);
            const float4* Ma = M + a * 5;
            #pragma unroll
            for (int j = 0; j < 5; j++) {
                const float4 m = Ma[j];     // one LDS.128 -> 2 FFMA2
                acc[2 * j]     = ffma2(va2, make_float2(m.x, m.y), acc[2 * j]);
                acc[2 * j + 1] = ffma2(va2, make_float2(m.z, m.w), acc[2 * j + 1]);
            }
        }
        #pragma unroll
        for (int c = 0; c < 10; c++)
            v[c] = fmaf(sn, acc[c].y, cn * acc[c].x);
    }

    float ce, se;
    __sincosf(f[8] * PI_HALF, &se, &ce);
    float r = 0.f;
    #pragma unroll
    for (int a = 0; a < 10; a++)
        r = fmaf(v[a], fmaf(se, sWn[2 * a + 1], ce * sWn[2 * a]), r);
    return r;
}

// ---------------- single fused kernel ----------------
// launch_bounds(128,5): 102-reg cap, 5 resident blocks/SM -> grid 5*SMs (=740)
// covers all 729 phase-0 pixels in ONE wave, and the grid barrier is safe.
__global__ void __launch_bounds__(NT, 5)
fused_lotenet(const float* __restrict__ x,
              const float* __restrict__ W00, const float* __restrict__ Wm0, const float* __restrict__ Wn0,
              const float* __restrict__ W01, const float* __restrict__ Wm1, const float* __restrict__ Wn1,
              const float* __restrict__ W02, const float* __restrict__ Wm2, const float* __restrict__ Wn2,
              const float* __restrict__ W03, const float* __restrict__ Wm3, const float* __restrict__ Wn3,
              float* __restrict__ out)
{
    __shared__ __align__(16) float sWm[1400];    // compute layout
    __shared__ __align__(16) float sRaw[1664];   // cp.async landing zone
    __shared__ __align__(16) float sW0[200];
    __shared__ float sWn[20];

    const int tid = threadIdx.x;   // sample b
    const int bid = blockIdx.x;
    const int nblk = gridDim.x;

    float f[9];

    // ---- Phase 0: layer-0 MPS, one pixel per block (single wave) ----
    for (int n = bid; n < 729; n += nblk) {
        __syncthreads();
        stage_wm_g(Wm0 + n * 1400, sWm, tid);
        if (tid < 20)      sW0[tid]      = W00[n * 20 + tid];
        else if (tid < 40) sWn[tid - 20] = Wn0[n * 20 + (tid - 20)];
        __syncthreads();

        const int i = n / 27, j = n - i * 27;
        #pragma unroll
        for (int k = 0; k < 9; k++) {
            const int r = 3 * i + k / 3;
            const int c = 3 * j + (k - (k / 3) * 3);
            f[k] = x[((size_t)tid * 81 + r) * 81 + c];
        }
        const float y = mps_core(f, sW0, sW0 + 10, sWm, sWn);
        g_y0[n * 128 + tid] = y;
        atomicMax(&g_kx0[tid * 32], fkey(y));
        atomicMax(&g_kn0[tid * 32], ~fkey(y));
    }

    // Prefetch phase-1 weights into sRaw; copies land while we spin in barrier.
    if (bid < 81) {
        const float* gWm = Wm1 + bid * 1400;
        const float* gW0 = W01 + bid * 20;
        const float* gWn = Wn1 + bid * 20;
        #pragma unroll
        for (int t = tid; t < 360; t += NT) {
            if (t < 350)      cp_async16(sRaw + t * 4,                 gWm + t * 4);
            else if (t < 355) cp_async16(sRaw + 1400 + (t - 350) * 4,  gW0 + (t - 350) * 4);
            else              cp_async16(sRaw + 1420 + (t - 355) * 4,  gWn + (t - 355) * 4);
        }
        CP_COMMIT();
    }
    grid_barrier();

    // ---- Phase 1: layer-1 MPS, 81 blocks ----
    if (bid < 81) {
        CP_WAIT0();
        __syncthreads();                     // all threads' copies visible
        stage_wm_s(sRaw, sWm, tid);
        if (tid < 20)      sW0[tid]      = sRaw[1400 + tid];
        else if (tid < 40) sWn[tid - 20] = sRaw[1420 + (tid - 20)];

        const float mn = funkey(~g_kn0[tid * 32]);
        const float iv = 1.0f / (funkey(g_kx0[tid * 32]) - mn);
        __syncthreads();

        const int n = bid;
        const int i = n / 9, j = n - i * 9;
        #pragma unroll
        for (int k = 0; k < 9; k++) {
            const int r = 3 * i + k / 3;
            const int c = 3 * j + (k - (k / 3) * 3);
            f[k] = (g_y0[(r * 27 + c) * 128 + tid] - mn) * iv;
        }
        const float y = mps_core(f, sW0, sW0 + 10, sWm, sWn);
        g_y1[n * 128 + tid] = y;
        atomicMax(&g_kx1[tid * 32], fkey(y));
        atomicMax(&g_kn1[tid * 32], ~fkey(y));

        // Prefetch phase-2 weights (blocks 0..8).
        if (bid < 9) {
            __syncthreads();                 // sRaw dead for all warps now
            const float* gWm = Wm2 + bid * 1400;
            const float* gW0 = W02 + bid * 20;
            const float* gWn = Wn2 + bid * 20;
            #pragma unroll
            for (int t = tid; t < 360; t += NT) {
                if (t < 350)      cp_async16(sRaw + t * 4,                gWm + t * 4);
                else if (t < 355) cp_async16(sRaw + 1400 + (t - 350) * 4, gW0 + (t - 350) * 4);
                else              cp_async16(sRaw + 1420 + (t - 355) * 4, gWn + (t - 355) * 4);
            }
            CP_COMMIT();
        }
    }
    grid_barrier();

    // ---- Phase 2: layer-2 MPS, 9 blocks. Last block resets L0 keys. ----
    if (bid < 9) {
        CP_WAIT0();
        __syncthreads();
        stage_wm_s(sRaw, sWm, tid);
        if (tid < 20)      sW0[tid]      = sRaw[1400 + tid];
        else if (tid < 40) sWn[tid - 20] = sRaw[1420 + (tid - 20)];

        const float mn = funkey(~g_kn1[tid * 32]);
        const float iv = 1.0f / (funkey(g_kx1[tid * 32]) - mn);
        __syncthreads();

        const int n = bid;
        const int i = n / 3, j = n - i * 3;
        #pragma unroll
        for (int k = 0; k < 9; k++) {
            const int r = 3 * i + k / 3;
            const int c = 3 * j + (k - (k / 3) * 3);
            f[k] = (g_y1[(r * 9 + c) * 128 + tid] - mn) * iv;
        }
        g_y2[n * 128 + tid] = mps_core(f, sW0, sW0 + 10, sWm, sWn);
    } else if (bid == nblk - 1) {
        g_kx0[tid * 32] = 0;
        g_kn0[tid * 32] = 0;
    }
    // Prefetch final-layer weights (blocks 0..9); block 9 was idle above.
    if (bid < 10) {
        if (bid < 9) __syncthreads();        // ensure sRaw no longer read
        #pragma unroll
        for (int t = tid; t < 405; t += NT) {
            if (t < 350)      cp_async16(sRaw + t * 4,                Wm3 + t * 4);
            else if (t < 400) cp_async16(sRaw + 1400 + (t - 350) * 4, W03 + (t - 350) * 4);
            else              cp_async16(sRaw + 1600 + (t - 400) * 4, Wn3 + (t - 400) * 4);
        }
        CP_COMMIT();
    }
    grid_barrier();

    // ---- Phase 3: final MPS (O=10), 10 blocks. Last block resets L1 keys. ----
    if (bid < 10) {
        CP_WAIT0();
        __syncthreads();
        stage_wm_s(sRaw, sWm, tid);
        #pragma unroll
        for (int t = tid; t < 200; t += NT) sW0[t] = sRaw[1400 + t];
        if (tid < 20) sWn[tid] = sRaw[1600 + tid];

        float yk[9];
        float mn = INFINITY, mx = -INFINITY;
        #pragma unroll
        for (int k = 0; k < 9; k++) {
            yk[k] = g_y2[k * 128 + tid];
            mn = fminf(mn, yk[k]);
            mx = fmaxf(mx, yk[k]);
        }
        const float iv = 1.0f / (mx - mn);
        __syncthreads();

        #pragma unroll
        for (int k = 0; k < 9; k++) f[k] = (yk[k] - mn) * iv;

        const int o = bid;
        out[tid * 10 + o] = mps_core(f, sW0 + o * 10, sW0 + 100 + o * 10, sWm, sWn);
    } else if (bid == nblk - 1) {
        g_kx1[tid * 32] = 0;
        g_kn1[tid * 32] = 0;
    }
}

extern "C" void kernel_launch(void* const* d_in, const int* in_sizes, int n_in,
                              void* d_out, int out_size)
{
    const float* x   = (const float*)d_in[0];
    const float* W00 = (const float*)d_in[1];
    const float* Wm0 = (const float*)d_in[2];
    const float* Wn0 = (const float*)d_in[3];
    const float* W01 = (const float*)d_in[6];
    const float* Wm1 = (const float*)d_in[7];
    const float* Wn1 = (const float*)d_in[8];
    const float* W02 = (const float*)d_in[11];
    const float* Wm2 = (const float*)d_in[12];
    const float* Wn2 = (const float*)d_in[13];
    const float* W03 = (const float*)d_in[16];
    const float* Wm3 = (const float*)d_in[17];
    const float* Wn3 = (const float*)d_in[18];

    int nsm = 148;
    cudaDeviceGetAttribute(&nsm, cudaDevAttrMultiProcessorCount, 0);
    const int grid = 5 * nsm;   // __launch_bounds__(128,5): all resident

    fused_lotenet<<<grid, NT>>>(x, W00, Wm0, Wn0, W01, Wm1, Wn1,
                                W02, Wm2, Wn2, W03, Wm3, Wn3,
                                (float*)d_out);
}